// round 3
// baseline (speedup 1.0000x reference)
#include <cuda_runtime.h>
#include <cuda_fp16.h>

#define H       2048
#define TSTEPS  4098        // N + 2 rows of xs
#define GRID    148
#define THREADS 512
#define MAXR    56          // 4 gates * 14 h-indices max per block
#define KS      1536        // halves per W_hh row kept in SMEM (blocks 0..5)
                            // blocks 6,7 (512 halves/row) live in registers

// Hidden state published between blocks, fp16, double-buffered.
__device__ __align__(16) __half g_h[2][H];
// Dense decentralized barrier flags (monotonic across graph replays).
__device__ unsigned g_flag[GRID];

struct SmemLayout {
    __half w[MAXR][KS];     // 172032 B
    __half hst[H];          // 4096 B staged hidden state
    float  bias[MAXR];      // b_ih + b_hh
    float  wih[MAXR][3];    // W_ih rows
};

__device__ __forceinline__ __half2 u2h2(unsigned u) {
    return *reinterpret_cast<__half2*>(&u);
}

__global__ void __launch_bounds__(THREADS, 1)
lstm_persistent_kernel(const float* __restrict__ seq,
                       const float* __restrict__ Wih,
                       const float* __restrict__ Whh,
                       const float* __restrict__ bih,
                       const float* __restrict__ bhh,
                       float* __restrict__ out)
{
    extern __shared__ char smem_raw[];
    SmemLayout& S = *reinterpret_cast<SmemLayout*>(smem_raw);

    const int b    = blockIdx.x;
    const int tid  = threadIdx.x;
    const int lane = tid & 31;
    const int wrp  = tid >> 5;

    // Block b owns h indices j = b + GRID*i, i in [0, nj). Warp i owns index i:
    // local rows r = 4*i + g  (all 4 gates of one h-index in one warp).
    const int nj = (H - 1 - b) / GRID + 1;   // 14 for b<124, else 13
    const int R  = 4 * nj;

    // ---- One-time init ----
    for (int r = 0; r < R; r++) {
        const int i    = r >> 2;
        const int g    = r & 3;
        const int grow = g * H + b + GRID * i;
        const float* src = Whh + (size_t)grow * H;
        for (int k = tid; k < KS; k += THREADS)
            S.w[r][k] = __float2half_rn(src[k]);
        if (tid == 0) S.bias[r] = bih[grow] + bhh[grow];
        if (tid < 3)  S.wih[r][tid] = Wih[grow * 3 + tid];
    }

    // Register-resident tail of each row: uint4-blocks 6 and 7.
    // Block mm covers halves [256*mm + 8*lane, +8).
    uint4 wreg6[4], wreg7[4];
    if (wrp < nj) {
#pragma unroll
        for (int g = 0; g < 4; g++) {
            const float* src = Whh + (size_t)(g * H + b + GRID * wrp) * H;
            const float* p6 = src + 256 * 6 + 8 * lane;
            const float* p7 = src + 256 * 7 + 8 * lane;
            __half2 h0, h1, h2_, h3;
            h0 = __floats2half2_rn(p6[0], p6[1]);
            h1 = __floats2half2_rn(p6[2], p6[3]);
            h2_= __floats2half2_rn(p6[4], p6[5]);
            h3 = __floats2half2_rn(p6[6], p6[7]);
            wreg6[g] = make_uint4(*(unsigned*)&h0, *(unsigned*)&h1,
                                  *(unsigned*)&h2_, *(unsigned*)&h3);
            h0 = __floats2half2_rn(p7[0], p7[1]);
            h1 = __floats2half2_rn(p7[2], p7[3]);
            h2_= __floats2half2_rn(p7[4], p7[5]);
            h3 = __floats2half2_rn(p7[6], p7[7]);
            wreg7[g] = make_uint4(*(unsigned*)&h0, *(unsigned*)&h1,
                                  *(unsigned*)&h2_, *(unsigned*)&h3);
        }
    }
    __syncthreads();

    const unsigned flag_base = *(volatile unsigned*)&g_flag[b];

    float cj = 0.0f;                 // replicated across all lanes of warp wrp
    float* hs_out = out + H;

    for (int t = 0; t < TSTEPS; t++) {
        // ---- load x for this step (overlaps with matvec) ----
        float x0 = 0.f, x1 = 0.f, x2 = 1.f;
        if (t >= 1 && t < TSTEPS - 1) {
            const float* sp = seq + (size_t)(t - 1) * 3;
            x0 = __ldg(sp); x1 = __ldg(sp + 1); x2 = __ldg(sp + 2);
        }

        float s0 = 0.f, s1 = 0.f, s2 = 0.f, s3 = 0.f;

        if (t > 0) {
            // ---- stage h: global (L2) -> SMEM, one cooperative pass ----
            reinterpret_cast<uint2*>(S.hst)[tid] =
                __ldcg(&reinterpret_cast<const uint2*>(g_h[t & 1])[tid]);
            __syncthreads();

            if (wrp < nj) {
                // fill h registers: block mm, lane -> uint4 idx 32*mm+lane
                uint4 hh[8];
                const uint4* h4 = reinterpret_cast<const uint4*>(S.hst);
#pragma unroll
                for (int m = 0; m < 8; m++) hh[m] = h4[32 * m + lane];

                float sr[4];
#pragma unroll
                for (int g = 0; g < 4; g++) {
                    const uint4* wrow =
                        reinterpret_cast<const uint4*>(&S.w[4 * wrp + g][0]);
                    __half2 a0 = __float2half2_rn(0.f);
                    __half2 a1 = a0, a2 = a0, a3 = a0;
#pragma unroll
                    for (int mm = 0; mm < 6; mm++) {
                        uint4 wv = wrow[32 * mm + lane];
                        a0 = __hfma2(u2h2(wv.x), u2h2(hh[mm].x), a0);
                        a1 = __hfma2(u2h2(wv.y), u2h2(hh[mm].y), a1);
                        a2 = __hfma2(u2h2(wv.z), u2h2(hh[mm].z), a2);
                        a3 = __hfma2(u2h2(wv.w), u2h2(hh[mm].w), a3);
                    }
                    {
                        uint4 wv = wreg6[g];
                        a0 = __hfma2(u2h2(wv.x), u2h2(hh[6].x), a0);
                        a1 = __hfma2(u2h2(wv.y), u2h2(hh[6].y), a1);
                        a2 = __hfma2(u2h2(wv.z), u2h2(hh[6].z), a2);
                        a3 = __hfma2(u2h2(wv.w), u2h2(hh[6].w), a3);
                    }
                    {
                        uint4 wv = wreg7[g];
                        a0 = __hfma2(u2h2(wv.x), u2h2(hh[7].x), a0);
                        a1 = __hfma2(u2h2(wv.y), u2h2(hh[7].y), a1);
                        a2 = __hfma2(u2h2(wv.z), u2h2(hh[7].z), a2);
                        a3 = __hfma2(u2h2(wv.w), u2h2(hh[7].w), a3);
                    }
                    float2 f0 = __half22float2(__hadd2(a0, a1));
                    float2 f1 = __half22float2(__hadd2(a2, a3));
                    float ss = (f0.x + f1.x) + (f0.y + f1.y);
#pragma unroll
                    for (int off = 16; off; off >>= 1)
                        ss += __shfl_xor_sync(0xffffffffu, ss, off);
                    sr[g] = ss;   // butterfly: all lanes hold the full sum
                }
                s0 = sr[0]; s1 = sr[1]; s2 = sr[2]; s3 = sr[3];
            }
        }

        // ---- in-warp combine: gates -> activations -> (c, h) -> publish ----
        if (wrp < nj) {
            const int g = lane & 3;
            const int r = 4 * wrp + g;
            float sv = (g == 0) ? s0 : (g == 1) ? s1 : (g == 2) ? s2 : s3;
            float act = 0.f;
            if (lane < 4) {
                float gate = sv + S.bias[r]
                           + S.wih[r][0] * x0 + S.wih[r][1] * x1
                           + S.wih[r][2] * x2;
                if (g == 2) act = tanhf(gate);
                else        act = 1.f / (1.f + __expf(-gate));
            }
            const float ig = __shfl_sync(0xffffffffu, act, 0);
            const float fg = __shfl_sync(0xffffffffu, act, 1);
            const float gg = __shfl_sync(0xffffffffu, act, 2);
            const float og = __shfl_sync(0xffffffffu, act, 3);
            cj = fg * cj + ig * gg;                 // uniform across lanes
            const float hj = og * tanhf(cj);

            if (lane == 0) {
                const int j = b + GRID * wrp;
                g_h[(t + 1) & 1][j] = __float2half_rn(hj);
                if (t >= 1)          hs_out[(size_t)(t - 1) * H + j] = hj;
                if (t == TSTEPS - 1) out[j] = hj;
            }
        }

        // ---- grid barrier (skip after last step) ----
        if (t < TSTEPS - 1) {
            __syncthreads();                        // publish stores done
            const unsigned target = flag_base + (unsigned)t + 1u;
            if (tid == 0) {
                __threadfence();
                *(volatile unsigned*)&g_flag[b] = target;
            }
            if (tid < 32) {
                bool done = false;
                while (!done) {
                    bool ok = true;
#pragma unroll
                    for (int k = 0; k < 5; k++) {
                        const int idx = lane + 32 * k;
                        if (idx < GRID) {
                            unsigned f = __ldcg(&g_flag[idx]);
                            if ((int)(f - target) < 0) ok = false;
                        }
                    }
                    done = __all_sync(0xffffffffu, ok);
                    if (!done) __nanosleep(32);
                }
                __threadfence();
            }
            __syncthreads();
        }
    }
}

extern "C" void kernel_launch(void* const* d_in, const int* in_sizes, int n_in,
                              void* d_out, int out_size)
{
    const float* seq = (const float*)d_in[0];
    const float* Wih = (const float*)d_in[1];
    const float* Whh = (const float*)d_in[2];
    const float* bih = (const float*)d_in[3];
    const float* bhh = (const float*)d_in[4];
    float* out = (float*)d_out;

    const size_t smem = sizeof(SmemLayout);
    cudaFuncSetAttribute(lstm_persistent_kernel,
                         cudaFuncAttributeMaxDynamicSharedMemorySize, (int)smem);
    lstm_persistent_kernel<<<GRID, THREADS, smem>>>(seq, Wih, Whh, bih, bhh, out);
}